// round 17
// baseline (speedup 1.0000x reference)
#include <cuda_runtime.h>

#define HALFW 6
#define MAXC  63
#define NK    21
#define NB    64
#define NC    256
#define CG    16                  // channels per block
#define NCG   (NC / CG)           // 16 channel groups
#define NH    64
#define NW    64
#define HW    (NH * NW)
#define HW4   (HW / 4)            // 1024 float4 per channel
#define NBLK  (NCG * NB * 2)      // 2048 blocks
#define FULLM 0xffffffffu

// Scratch (allocation-free rule: __device__ globals; zero-initialized)
__device__ float g_part[2][NK][NCG][NB];  // [t][k][cg][b], coalesced finisher
__device__ int   g_done = 0;              // grid completion (self-resetting)

// ---------------------------------------------------------------------------
// Single fused kernel. grid = (16, 64, 2), block = 256.
// Block = (t, b, 16-channel group): reads ONE CONTIGUOUS 256KB slab
// (memcpy-like stream), accumulating per-cell channel sums in registers.
// Thread owns 4 fixed float4 positions (q = tid + 256r), each predicated on
// its 128B line intersecting any of the 21 boxes (~7% byte skip preserved).
// Then: stage 16KB cell-sum tile in smem -> full-box partials (x 1/cnt)
// -> g_part; last of 2048 blocks reduces coalesced + computes MSE.
// ---------------------------------------------------------------------------
__global__ void __launch_bounds__(256) fused_kernel(
    const float* __restrict__ f1, const float* __restrict__ f2,
    const int* __restrict__ pre1, const int* __restrict__ pre2,
    float* __restrict__ out)
{
    const int t   = blockIdx.z;
    const int b   = blockIdx.y;
    const int cg  = blockIdx.x;
    const int tid = threadIdx.x;

    __shared__ __align__(16) float s_sum[HW];   // per-cell 16-ch sums, 16KB
    __shared__ int s_pre[2 * NK];

    const int* __restrict__ pre = (t == 0) ? pre1 : pre2;
    if (tid < 2 * NK) s_pre[tid] = pre[b * 2 * NK + tid];
    __syncthreads();

    // ---- per-position need bits (line granularity: 128B = 8 float4) ----
    bool need[4];
#pragma unroll
    for (int r = 0; r < 4; ++r) {
        const int q  = tid + 256 * r;         // float4 index 0..1023
        const int h  = q >> 4;                // row
        const int c0 = ((q >> 3) & 1) * 32;   // half-row col base
        bool nd = false;
#pragma unroll
        for (int k = 0; k < NK; ++k) {
            const int x = s_pre[2 * k + 0];
            const int y = s_pre[2 * k + 1];
            const int left  = max(x - HALFW, 0);
            const int right = min(x + HALFW, MAXC);   // exclusive
            const int down  = max(y - HALFW, 0);
            const int up    = min(y + HALFW, MAXC);   // exclusive
            nd |= (h >= left) & (h < right) & (down < c0 + 32) & (up > c0);
        }
        need[r] = nd;
    }

    // ---- contiguous 256KB slab stream: 16 channels x 4 float4/thread ----
    const float4* __restrict__ f4 =
        reinterpret_cast<const float4*>(t == 0 ? f1 : f2);
    const float4* __restrict__ slab =
        f4 + (size_t)(b * NC + cg * CG) * HW4 + tid;

    float4 a0 = make_float4(0.f, 0.f, 0.f, 0.f);
    float4 a1 = a0, a2 = a0, a3 = a0;
#pragma unroll 4
    for (int c = 0; c < CG; ++c) {
        const float4* __restrict__ p = slab + (size_t)c * HW4;
        if (need[0]) { float4 v = p[0];
            a0.x += v.x; a0.y += v.y; a0.z += v.z; a0.w += v.w; }
        if (need[1]) { float4 v = p[256];
            a1.x += v.x; a1.y += v.y; a1.z += v.z; a1.w += v.w; }
        if (need[2]) { float4 v = p[512];
            a2.x += v.x; a2.y += v.y; a2.z += v.z; a2.w += v.w; }
        if (need[3]) { float4 v = p[768];
            a3.x += v.x; a3.y += v.y; a3.z += v.z; a3.w += v.w; }
    }

    // ---- stage (x 1/NC) to smem tile ----
    {
        const float sc = 1.0f / (float)NC;
        float4* __restrict__ s4 = reinterpret_cast<float4*>(s_sum);
        s4[tid + 0]   = make_float4(a0.x*sc, a0.y*sc, a0.z*sc, a0.w*sc);
        s4[tid + 256] = make_float4(a1.x*sc, a1.y*sc, a1.z*sc, a1.w*sc);
        s4[tid + 512] = make_float4(a2.x*sc, a2.y*sc, a2.z*sc, a2.w*sc);
        s4[tid + 768] = make_float4(a3.x*sc, a3.y*sc, a3.z*sc, a3.w*sc);
    }
    __syncthreads();

    // ---- full-box partials (x 1/cnt): warp-per-keypoint, div-free 12x12 ----
    const int warp = tid >> 5;
    const int lane = tid & 31;
    for (int k = warp; k < NK; k += 8) {
        const int x = s_pre[2 * k + 0];
        const int y = s_pre[2 * k + 1];
        const int left  = max(x - HALFW, 0);
        const int right = min(x + HALFW, MAXC);
        const int down  = max(y - HALFW, 0);
        const int up    = min(y + HALFW, MAXC);
        const int nh = right - left;          // 6..12
        const int nw = up - down;             // 6..12
        const float inv_cnt = 1.0f / (float)(nh * nw);

        float s = 0.f;
#pragma unroll
        for (int it = 0; it < 5; ++it) {
            const int idx = lane + 32 * it;   // 0..159
            const int r = idx / 12;           // constant divisor -> mul/shift
            const int c = idx - r * 12;
            if ((idx < 144) && (r < nh) && (c < nw))
                s += s_sum[(left + r) * NW + (down + c)];
        }
#pragma unroll
        for (int off = 16; off > 0; off >>= 1)
            s += __shfl_down_sync(FULLM, s, off);
        if (lane == 0)
            g_part[t][k][cg][b] = s * inv_cnt;    // written exactly once
    }

    // ---- grid completion: last of 2048 blocks finishes ----
    __shared__ int s_last;
    if (lane == 0) __threadfence();           // order this warp's g_part store
    __syncthreads();
    if (tid == 0)
        s_last = (atomicAdd(&g_done, 1) == NBLK - 1) ? 1 : 0;
    __syncthreads();
    if (!s_last) return;

    __threadfence();
    __shared__ float s_fea[2 * NK];
    // warp per (t,k); lanes read consecutive b -> fully coalesced
    for (int g = warp; g < 2 * NK; g += 8) {
        const int tt = g / NK;
        const int kk = g - tt * NK;
        float v = 0.f;
#pragma unroll
        for (int c = 0; c < NCG; ++c) {
            v += __ldcg(&g_part[tt][kk][c][lane]);
            v += __ldcg(&g_part[tt][kk][c][lane + 32]);
        }
#pragma unroll
        for (int off = 16; off > 0; off >>= 1)
            v += __shfl_down_sync(FULLM, v, off);
        if (lane == 0)
            s_fea[g] = v * (1.0f / (float)NB);
    }
    __syncthreads();
    if (tid == 0) {
        float acc2 = 0.f;
#pragma unroll
        for (int kk = 0; kk < NK; ++kk) {
            const float d = s_fea[kk] - 0.999f * s_fea[NK + kk];
            acc2 += d * d;
        }
        out[0] = acc2 * (1.0f / (float)NK);
        g_done = 0;                           // reset for next replay
    }
}

extern "C" void kernel_launch(void* const* d_in, const int* in_sizes, int n_in,
                              void* d_out, int out_size)
{
    const float* f1   = (const float*)d_in[0];
    const float* f2   = (const float*)d_in[1];
    const int*   pre1 = (const int*)d_in[2];
    const int*   pre2 = (const int*)d_in[3];

    fused_kernel<<<dim3(NCG, NB, 2), 256>>>(f1, f2, pre1, pre2, (float*)d_out);
}